// round 15
// baseline (speedup 1.0000x reference)
#include <cuda_runtime.h>
#include <cuda_fp16.h>
#include <cstdint>

// Problem constants
#define NROWS   8192
#define IN_F    4096
#define OUT_F   4096
#define E_NUM   8
#define R_PER   16
#define R_TOT   128              // E_NUM * R_PER
#define KCAT    (IN_F + R_TOT)   // 4224
#define P_COLS  (E_NUM + R_TOT)  // 136
#define SCALING 0.125f           // 16 / 128
#define KSPLIT  4                // split-K for skinny gate GEMM

// -------- device scratch (allocation-free rule: __device__ globals) --------
__device__ __align__(1024) __half g_Xcat[(size_t)NROWS * KCAT];  // [8192,4224] [x | H]
__device__ __align__(1024) __half g_Wcat[(size_t)OUT_F * KCAT];  // [4096,4224] [W0 | Bmat]
__device__ __align__(1024) __half g_WgA [(size_t)P_COLS * IN_F]; // [136,4096]  [Wg ; A]
__device__ float g_P[(size_t)KSPLIT * NROWS * P_COLS];           // split-K partials

__device__ __forceinline__ uint32_t smem_u32(const void* p) {
    return (uint32_t)__cvta_generic_to_shared(p);
}
__device__ __forceinline__ void cp16(uint32_t dst, const void* src, bool pred) {
    int sz = pred ? 16 : 0;   // src-size 0 -> zero-fill
    asm volatile("cp.async.cg.shared.global [%0], [%1], 16, %2;\n" :: "r"(dst), "l"(src), "r"(sz));
}
__device__ __forceinline__ void ldsm_x4(uint32_t& r0, uint32_t& r1, uint32_t& r2, uint32_t& r3,
                                        uint32_t addr) {
    asm volatile("ldmatrix.sync.aligned.m8n8.x4.shared.b16 {%0,%1,%2,%3}, [%4];\n"
                 : "=r"(r0), "=r"(r1), "=r"(r2), "=r"(r3) : "r"(addr));
}

// ======== conversion: x -> Xcat  AND  [Wg;A] -> WgA in one kernel ========
__global__ void conv_x_kernel(const float4* __restrict__ x,
                              const float* __restrict__ Wg, const float* __restrict__ A,
                              __half* __restrict__ Xcat, __half* __restrict__ WgA) {
    int64_t total = (int64_t)NROWS * IN_F / 4;
    for (int64_t i = (int64_t)blockIdx.x * blockDim.x + threadIdx.x; i < total;
         i += (int64_t)gridDim.x * blockDim.x) {
        float4 v = x[i];
        int64_t e = i << 2;
        int n = (int)(e >> 12);
        int k = (int)(e & 4095);
        __half2 h0 = __floats2half2_rn(v.x, v.y);
        __half2 h1 = __floats2half2_rn(v.z, v.w);
        uint2 pk;
        pk.x = *(uint32_t*)&h0; pk.y = *(uint32_t*)&h1;
        *(uint2*)&Xcat[(int64_t)n * KCAT + k] = pk;   // single 8B store
    }
    int64_t wtotal = (int64_t)P_COLS * IN_F;
    for (int64_t i = (int64_t)blockIdx.x * blockDim.x + threadIdx.x; i < wtotal;
         i += (int64_t)gridDim.x * blockDim.x) {
        int j = (int)(i >> 12);
        int k = (int)(i & 4095);
        float v = (j < E_NUM) ? Wg[(int64_t)j * IN_F + k]
                              : A[(int64_t)(j - E_NUM) * IN_F + k];
        WgA[i] = __float2half_rn(v);
    }
}

// ======= softmax + split-K reduce + pack H into Xcat =======
__global__ void softmax_pack_kernel(const float* __restrict__ P, __half* __restrict__ Xcat) {
    int n = blockIdx.x;
    int t = threadIdx.x;
    __shared__ float gate[E_NUM];
    const int64_t zs = (int64_t)NROWS * P_COLS;
    if (t == 0) {
        float l[E_NUM];
        float mx = -1e30f;
        #pragma unroll
        for (int e = 0; e < E_NUM; e++) {
            float s = 0.f;
            #pragma unroll
            for (int z = 0; z < KSPLIT; z++) s += P[z * zs + (int64_t)n * P_COLS + e];
            l[e] = s; mx = fmaxf(mx, s);
        }
        float s = 0.f;
        #pragma unroll
        for (int e = 0; e < E_NUM; e++) { l[e] = expf(l[e] - mx); s += l[e]; }
        float inv = 1.0f / s;
        #pragma unroll
        for (int e = 0; e < E_NUM; e++) gate[e] = l[e] * inv;
    }
    __syncthreads();
    float h = 0.f;
    #pragma unroll
    for (int z = 0; z < KSPLIT; z++) h += P[z * zs + (int64_t)n * P_COLS + E_NUM + t];
    int e = t >> 4;
    Xcat[(int64_t)n * KCAT + IN_F + t] = __float2half_rn(SCALING * gate[e] * h);
}

// ============ skinny GEMM (128x128, 8 warps, 5-stage, split-K) ============
// + tail: each of the 512 CTAs converts its 1/512 slice of W0/Bmat into Wcat
//   (overlaps other CTAs' GEMM work; Wcat needed only by gemm_big, launched later).
#define BM 128
#define BN 128
#define BK 32
#define SLD 40
#define STG 5
#define STAGE_HALVES (BM * SLD)
#define DYN_SMEM (2 * STG * STAGE_HALVES * 2)

__global__ __launch_bounds__(256, 2)
void gemm_f16_ms(const __half* __restrict__ A, const __half* __restrict__ B,
                 float* __restrict__ C,
                 const float4* __restrict__ W0src, const float* __restrict__ Bsrc,
                 __half* __restrict__ Wcat,
                 int M, int N, int K, int lda, int ldb, int ldc) {
    extern __shared__ __half sm[];
    __half* As = sm;
    __half* Bs = sm + STG * STAGE_HALVES;

    const int tid  = threadIdx.x;
    const int warp = tid >> 5;
    const int lane = tid & 31;
    const int g    = lane >> 2;
    const int tg   = lane & 3;
    const int lm   = lane & 7;
    const int wm   = (warp & 3) * 32;
    const int wn   = (warp >> 2) * 64;
    const int bm   = blockIdx.y * BM;
    const int bn   = blockIdx.x * BN;
    const int zoff = blockIdx.z * K;
    float* Cz = C + (int64_t)blockIdx.z * (int64_t)M * ldc;

    const int lr = tid >> 2;
    const int lc = (tid & 3) * 8;

    float acc[2][8][4];
    #pragma unroll
    for (int mf = 0; mf < 2; mf++)
        #pragma unroll
        for (int nf = 0; nf < 8; nf++)
            #pragma unroll
            for (int i = 0; i < 4; i++) acc[mf][nf][i] = 0.f;

    const int nt = K / BK;
    const int a_row_off = ((lane >> 3) & 1) * 8 + lm;
    const int a_col_off = (lane >> 4) * 8;
    const int b_row_off = (lane >> 4) * 8 + lm;
    const int b_col_off = ((lane >> 3) & 1) * 8;

    auto load_stage = [&](int s, int k0) {
        __half* Ast = As + s * STAGE_HALVES;
        __half* Bst = Bs + s * STAGE_HALVES;
        #pragma unroll
        for (int i = 0; i < 2; i++) {
            int row = lr + i * 64;
            cp16(smem_u32(&Ast[row * SLD + lc]),
                 A + (int64_t)(bm + row) * lda + zoff + k0 + lc, true);
        }
        #pragma unroll
        for (int i = 0; i < 2; i++) {
            int row = lr + i * 64;
            cp16(smem_u32(&Bst[row * SLD + lc]),
                 B + (int64_t)(bn + row) * ldb + zoff + k0 + lc, (bn + row) < N);
        }
        asm volatile("cp.async.commit_group;\n");
    };

    #pragma unroll
    for (int s = 0; s < STG - 1; s++) load_stage(s, s * BK);

    for (int t = 0; t < nt; t++) {
        const int s = t % STG;
        asm volatile("cp.async.wait_group %0;\n" :: "n"(STG - 2));
        __syncthreads();   // single barrier: orders prev-stage reads before refill

        int tn = t + STG - 1;
        if (tn < nt) load_stage(tn % STG, tn * BK);

        const __half* Ast = As + s * STAGE_HALVES;
        const __half* Bst = Bs + s * STAGE_HALVES;
        #pragma unroll
        for (int kk = 0; kk < BK; kk += 16) {
            uint32_t a[2][4], b[8][2];
            #pragma unroll
            for (int mf = 0; mf < 2; mf++) {
                uint32_t addr = smem_u32(&Ast[(wm + mf * 16 + a_row_off) * SLD + kk + a_col_off]);
                ldsm_x4(a[mf][0], a[mf][1], a[mf][2], a[mf][3], addr);
            }
            #pragma unroll
            for (int p = 0; p < 4; p++) {
                uint32_t addr = smem_u32(&Bst[(wn + p * 16 + b_row_off) * SLD + kk + b_col_off]);
                ldsm_x4(b[2 * p][0], b[2 * p][1], b[2 * p + 1][0], b[2 * p + 1][1], addr);
            }
            #pragma unroll
            for (int mf = 0; mf < 2; mf++)
                #pragma unroll
                for (int nf = 0; nf < 8; nf++)
                    asm volatile(
                        "mma.sync.aligned.m16n8k16.row.col.f32.f16.f16.f32 "
                        "{%0,%1,%2,%3}, {%4,%5,%6,%7}, {%8,%9}, {%0,%1,%2,%3};\n"
                        : "+f"(acc[mf][nf][0]), "+f"(acc[mf][nf][1]),
                          "+f"(acc[mf][nf][2]), "+f"(acc[mf][nf][3])
                        : "r"(a[mf][0]), "r"(a[mf][1]), "r"(a[mf][2]), "r"(a[mf][3]),
                          "r"(b[nf][0]), "r"(b[nf][1]));
        }
    }

    #pragma unroll
    for (int mf = 0; mf < 2; mf++) {
        int r0 = bm + wm + mf * 16 + g;
        #pragma unroll
        for (int nf = 0; nf < 8; nf++) {
            int c = bn + wn + nf * 8 + 2 * tg;
            if (c + 1 < N) {
                __stcs((float2*)&Cz[(int64_t)r0 * ldc + c],
                       make_float2(acc[mf][nf][0], acc[mf][nf][1]));
                __stcs((float2*)&Cz[(int64_t)(r0 + 8) * ldc + c],
                       make_float2(acc[mf][nf][2], acc[mf][nf][3]));
            } else if (c < N) {
                Cz[(int64_t)r0 * ldc + c]       = acc[mf][nf][0];
                Cz[(int64_t)(r0 + 8) * ldc + c] = acc[mf][nf][2];
            }
        }
    }

    // ---- tail: convert this CTA's 1/512 slice of W0 + Bmat into Wcat ----
    {
        // grid is (2, 64, KSPLIT=4) -> 512 CTAs
        int cta = (blockIdx.z * 64 + blockIdx.y) * 2 + blockIdx.x;   // 0..511
        int64_t base = (int64_t)cta * 8192;                          // 8192 float4 per CTA
        for (int it = tid; it < 8192; it += 256) {
            int64_t i = base + it;
            float4 v = W0src[i];
            int64_t e = i << 2;
            int o = (int)(e >> 12);
            int c = (int)(e & 4095);
            __half2 h0 = __floats2half2_rn(v.x, v.y);
            __half2 h1 = __floats2half2_rn(v.z, v.w);
            uint2 pk;
            pk.x = *(uint32_t*)&h0; pk.y = *(uint32_t*)&h1;
            *(uint2*)&Wcat[(int64_t)o * KCAT + c] = pk;
        }
        int64_t bbase = (int64_t)cta * 1024;                         // 1024 Bmat elems per CTA
        for (int it = tid; it < 1024; it += 256) {
            int64_t i = bbase + it;
            int o  = (int)(i >> 7);
            int cc = (int)(i & 127);
            int e = cc >> 4, r = cc & 15;
            Wcat[(int64_t)o * KCAT + IN_F + cc] =
                __float2half_rn(Bsrc[((int64_t)e * OUT_F + o) * R_PER + r]);
        }
    }
}

// ===== MAIN GEMM: R9-EXACT (128x128, 8 warps, BK=32, 5 stages, 2 CTA/SM,
//       compile-time strides, single barrier per k-tile, streaming stores) =====
#define GNT (KCAT / BK)     // 132

__global__ __launch_bounds__(256, 2)
void gemm_big(const __half* __restrict__ A, const __half* __restrict__ B,
              float* __restrict__ C) {
    extern __shared__ __half sm[];
    __half* As = sm;
    __half* Bs = sm + STG * STAGE_HALVES;

    const int tid  = threadIdx.x;
    const int warp = tid >> 5;
    const int lane = tid & 31;
    const int g    = lane >> 2;
    const int tg   = lane & 3;
    const int lm   = lane & 7;
    const int wm   = (warp & 3) * 32;   // 4 warps along M
    const int wn   = (warp >> 2) * 64;  // 2 warps along N
    const int bm   = blockIdx.y * BM;
    const int bn   = blockIdx.x * BN;

    const int lr = tid >> 2;
    const int lc = (tid & 3) * 8;

    float acc[2][8][4];
    #pragma unroll
    for (int mf = 0; mf < 2; mf++)
        #pragma unroll
        for (int nf = 0; nf < 8; nf++)
            #pragma unroll
            for (int i = 0; i < 4; i++) acc[mf][nf][i] = 0.f;

    const int a_row_off = ((lane >> 3) & 1) * 8 + lm;
    const int a_col_off = (lane >> 4) * 8;
    const int b_row_off = (lane >> 4) * 8 + lm;
    const int b_col_off = ((lane >> 3) & 1) * 8;

    auto load_stage = [&](int s, int k0) {
        __half* Ast = As + s * STAGE_HALVES;
        __half* Bst = Bs + s * STAGE_HALVES;
        #pragma unroll
        for (int i = 0; i < 2; i++) {
            int row = lr + i * 64;
            cp16(smem_u32(&Ast[row * SLD + lc]),
                 A + (int64_t)(bm + row) * KCAT + k0 + lc, true);
        }
        #pragma unroll
        for (int i = 0; i < 2; i++) {
            int row = lr + i * 64;
            cp16(smem_u32(&Bst[row * SLD + lc]),
                 B + (int64_t)(bn + row) * KCAT + k0 + lc, true);
        }
        asm volatile("cp.async.commit_group;\n");
    };

    #pragma unroll
    for (int s = 0; s < STG - 1; s++) load_stage(s, s * BK);

    for (int t = 0; t < GNT; t++) {
        const int s = t % STG;
        asm volatile("cp.async.wait_group %0;\n" :: "n"(STG - 2));
        __syncthreads();   // single barrier: all warps done reading stage (t-1)%STG

        int tn = t + STG - 1;
        if (tn < GNT) load_stage(tn % STG, tn * BK);

        const __half* Ast = As + s * STAGE_HALVES;
        const __half* Bst = Bs + s * STAGE_HALVES;
        #pragma unroll
        for (int kk = 0; kk < BK; kk += 16) {
            uint32_t a[2][4], b[8][2];
            #pragma unroll
            for (int mf = 0; mf < 2; mf++) {
                uint32_t addr = smem_u32(&Ast[(wm + mf * 16 + a_row_off) * SLD + kk + a_col_off]);
                ldsm_x4(a[mf][0], a[mf][1], a[mf][2], a[mf][3], addr);
            }
            #pragma unroll
            for (int p = 0; p < 4; p++) {
                uint32_t addr = smem_u32(&Bst[(wn + p * 16 + b_row_off) * SLD + kk + b_col_off]);
                ldsm_x4(b[2 * p][0], b[2 * p][1], b[2 * p + 1][0], b[2 * p + 1][1], addr);
            }
            #pragma unroll
            for (int mf = 0; mf < 2; mf++)
                #pragma unroll
                for (int nf = 0; nf < 8; nf++)
                    asm volatile(
                        "mma.sync.aligned.m16n8k16.row.col.f32.f16.f16.f32 "
                        "{%0,%1,%2,%3}, {%4,%5,%6,%7}, {%8,%9}, {%0,%1,%2,%3};\n"
                        : "+f"(acc[mf][nf][0]), "+f"(acc[mf][nf][1]),
                          "+f"(acc[mf][nf][2]), "+f"(acc[mf][nf][3])
                        : "r"(a[mf][0]), "r"(a[mf][1]), "r"(a[mf][2]), "r"(a[mf][3]),
                          "r"(b[nf][0]), "r"(b[nf][1]));
        }
    }

    // epilogue: streaming stores (C is write-once; keep B resident in L2)
    #pragma unroll
    for (int mf = 0; mf < 2; mf++) {
        int r0 = bm + wm + mf * 16 + g;
        #pragma unroll
        for (int nf = 0; nf < 8; nf++) {
            int c = bn + wn + nf * 8 + 2 * tg;
            __stcs((float2*)&C[(int64_t)r0 * OUT_F + c],
                   make_float2(acc[mf][nf][0], acc[mf][nf][1]));
            __stcs((float2*)&C[(int64_t)(r0 + 8) * OUT_F + c],
                   make_float2(acc[mf][nf][2], acc[mf][nf][3]));
        }
    }
}

// ===================== launch =====================
extern "C" void kernel_launch(void* const* d_in, const int* in_sizes, int n_in,
                              void* d_out, int out_size) {
    const float* x  = (const float*)d_in[0];  // [8192, 4096]
    const float* W0 = (const float*)d_in[1];  // [4096, 4096]
    const float* Wg = (const float*)d_in[2];  // [8, 4096]
    const float* A  = (const float*)d_in[3];  // [8, 16, 4096]
    const float* B  = (const float*)d_in[4];  // [8, 4096, 16]
    float* out = (float*)d_out;               // [8192, 4096]

    __half *Xcat, *Wcat, *WgA;
    float* P;
    cudaGetSymbolAddress((void**)&Xcat, g_Xcat);
    cudaGetSymbolAddress((void**)&Wcat, g_Wcat);
    cudaGetSymbolAddress((void**)&WgA,  g_WgA);
    cudaGetSymbolAddress((void**)&P,    g_P);

    cudaFuncSetAttribute(gemm_f16_ms, cudaFuncAttributeMaxDynamicSharedMemorySize, DYN_SMEM);
    cudaFuncSetAttribute(gemm_big,    cudaFuncAttributeMaxDynamicSharedMemorySize, DYN_SMEM);

    // launch 1: x -> Xcat fp16  +  [Wg;A] -> WgA fp16
    conv_x_kernel<<<4096, 256>>>((const float4*)x, Wg, A, Xcat, WgA);

    // launch 2: skinny gate GEMM (split-K=4)  + W0/Bmat -> Wcat conversion tail
    gemm_f16_ms<<<dim3(2, NROWS / BM, KSPLIT), 256, DYN_SMEM>>>(
        Xcat, WgA, P, (const float4*)W0, B, Wcat,
        NROWS, P_COLS, IN_F / KSPLIT, KCAT, IN_F, P_COLS);

    // launch 3: softmax gate + split-K reduce + pack H
    softmax_pack_kernel<<<NROWS, 128>>>(P, Xcat);

    // launch 4: main GEMM (R9-exact)
    gemm_big<<<dim3(OUT_F / BN, NROWS / BM), 256, DYN_SMEM>>>(Xcat, Wcat, out);
}

// round 16
// speedup vs baseline: 1.5249x; 1.5249x over previous
#include <cuda_runtime.h>
#include <cuda_fp16.h>
#include <cstdint>

// Problem constants
#define NROWS   8192
#define IN_F    4096
#define OUT_F   4096
#define E_NUM   8
#define R_PER   16
#define R_TOT   128              // E_NUM * R_PER
#define KCAT    (IN_F + R_TOT)   // 4224
#define P_COLS  (E_NUM + R_TOT)  // 136
#define SCALING 0.125f           // 16 / 128
#define KSPLIT  4                // split-K for skinny gate GEMM

// -------- device scratch (allocation-free rule: __device__ globals) --------
__device__ __align__(1024) __half g_Xcat[(size_t)NROWS * KCAT];  // [8192,4224] [x | H]
__device__ __align__(1024) __half g_Wcat[(size_t)OUT_F * KCAT];  // [4096,4224] [W0 | Bmat]
__device__ __align__(1024) __half g_WgA [(size_t)P_COLS * IN_F]; // [136,4096]  [Wg ; A]
__device__ float g_P[(size_t)KSPLIT * NROWS * P_COLS];           // split-K partials

__device__ __forceinline__ uint32_t smem_u32(const void* p) {
    return (uint32_t)__cvta_generic_to_shared(p);
}
__device__ __forceinline__ void cp16(uint32_t dst, const void* src, bool pred) {
    int sz = pred ? 16 : 0;   // src-size 0 -> zero-fill
    asm volatile("cp.async.cg.shared.global [%0], [%1], 16, %2;\n" :: "r"(dst), "l"(src), "r"(sz));
}
__device__ __forceinline__ void ldsm_x4(uint32_t& r0, uint32_t& r1, uint32_t& r2, uint32_t& r3,
                                        uint32_t addr) {
    asm volatile("ldmatrix.sync.aligned.m8n8.x4.shared.b16 {%0,%1,%2,%3}, [%4];\n"
                 : "=r"(r0), "=r"(r1), "=r"(r2), "=r"(r3) : "r"(addr));
}

// ======== conversion: x -> Xcat  AND  [Wg;A] -> WgA in one kernel ========
__global__ void conv_x_kernel(const float4* __restrict__ x,
                              const float* __restrict__ Wg, const float* __restrict__ A,
                              __half* __restrict__ Xcat, __half* __restrict__ WgA) {
    int64_t total = (int64_t)NROWS * IN_F / 4;
    for (int64_t i = (int64_t)blockIdx.x * blockDim.x + threadIdx.x; i < total;
         i += (int64_t)gridDim.x * blockDim.x) {
        float4 v = x[i];
        int64_t e = i << 2;
        int n = (int)(e >> 12);
        int k = (int)(e & 4095);
        __half2 h0 = __floats2half2_rn(v.x, v.y);
        __half2 h1 = __floats2half2_rn(v.z, v.w);
        uint2 pk;
        pk.x = *(uint32_t*)&h0; pk.y = *(uint32_t*)&h1;
        *(uint2*)&Xcat[(int64_t)n * KCAT + k] = pk;   // single 8B store
    }
    int64_t wtotal = (int64_t)P_COLS * IN_F;
    for (int64_t i = (int64_t)blockIdx.x * blockDim.x + threadIdx.x; i < wtotal;
         i += (int64_t)gridDim.x * blockDim.x) {
        int j = (int)(i >> 12);
        int k = (int)(i & 4095);
        float v = (j < E_NUM) ? Wg[(int64_t)j * IN_F + k]
                              : A[(int64_t)(j - E_NUM) * IN_F + k];
        WgA[i] = __float2half_rn(v);
    }
}

// W0 -> Wcat[:, :4096]  AND  B -> Wcat[:, 4096:4224]  in one kernel
__global__ void conv_w_kernel(const float4* __restrict__ W0, const float* __restrict__ B,
                              __half* __restrict__ Wcat) {
    int64_t total = (int64_t)OUT_F * IN_F / 4;
    for (int64_t i = (int64_t)blockIdx.x * blockDim.x + threadIdx.x; i < total;
         i += (int64_t)gridDim.x * blockDim.x) {
        float4 v = W0[i];
        int64_t e = i << 2;
        int o = (int)(e >> 12);
        int c = (int)(e & 4095);
        __half2 h0 = __floats2half2_rn(v.x, v.y);
        __half2 h1 = __floats2half2_rn(v.z, v.w);
        uint2 pk;
        pk.x = *(uint32_t*)&h0; pk.y = *(uint32_t*)&h1;
        *(uint2*)&Wcat[(int64_t)o * KCAT + c] = pk;   // single 8B store
    }
    int64_t btotal = (int64_t)OUT_F * R_TOT;
    for (int64_t i = (int64_t)blockIdx.x * blockDim.x + threadIdx.x; i < btotal;
         i += (int64_t)gridDim.x * blockDim.x) {
        int o  = (int)(i >> 7);
        int cc = (int)(i & 127);
        int e = cc >> 4, r = cc & 15;
        Wcat[(int64_t)o * KCAT + IN_F + cc] =
            __float2half_rn(B[((int64_t)e * OUT_F + o) * R_PER + r]);
    }
}

// ======= softmax + split-K reduce + pack H into Xcat =======
__global__ void softmax_pack_kernel(const float* __restrict__ P, __half* __restrict__ Xcat) {
    int n = blockIdx.x;
    int t = threadIdx.x;
    __shared__ float gate[E_NUM];
    const int64_t zs = (int64_t)NROWS * P_COLS;
    if (t == 0) {
        float l[E_NUM];
        float mx = -1e30f;
        #pragma unroll
        for (int e = 0; e < E_NUM; e++) {
            float s = 0.f;
            #pragma unroll
            for (int z = 0; z < KSPLIT; z++) s += P[z * zs + (int64_t)n * P_COLS + e];
            l[e] = s; mx = fmaxf(mx, s);
        }
        float s = 0.f;
        #pragma unroll
        for (int e = 0; e < E_NUM; e++) { l[e] = expf(l[e] - mx); s += l[e]; }
        float inv = 1.0f / s;
        #pragma unroll
        for (int e = 0; e < E_NUM; e++) gate[e] = l[e] * inv;
    }
    __syncthreads();
    float h = 0.f;
    #pragma unroll
    for (int z = 0; z < KSPLIT; z++) h += P[z * zs + (int64_t)n * P_COLS + E_NUM + t];
    int e = t >> 4;
    Xcat[(int64_t)n * KCAT + IN_F + t] = __float2half_rn(SCALING * gate[e] * h);
}

// ============ skinny GEMM (128x128, 8 warps, 5-stage, split-K) ============
// R6 geometry + R9 tricks: single barrier per k-tile, streaming stores.
#define BM 128
#define BN 128
#define BK 32
#define SLD 40
#define STG 5
#define STAGE_HALVES (BM * SLD)
#define DYN_SMEM (2 * STG * STAGE_HALVES * 2)

__global__ __launch_bounds__(256, 2)
void gemm_f16_ms(const __half* __restrict__ A, const __half* __restrict__ B,
                 float* __restrict__ C,
                 int M, int N, int K, int lda, int ldb, int ldc) {
    extern __shared__ __half sm[];
    __half* As = sm;
    __half* Bs = sm + STG * STAGE_HALVES;

    const int tid  = threadIdx.x;
    const int warp = tid >> 5;
    const int lane = tid & 31;
    const int g    = lane >> 2;
    const int tg   = lane & 3;
    const int lm   = lane & 7;
    const int wm   = (warp & 3) * 32;
    const int wn   = (warp >> 2) * 64;
    const int bm   = blockIdx.y * BM;
    const int bn   = blockIdx.x * BN;
    const int zoff = blockIdx.z * K;
    float* Cz = C + (int64_t)blockIdx.z * (int64_t)M * ldc;

    const int lr = tid >> 2;
    const int lc = (tid & 3) * 8;

    float acc[2][8][4];
    #pragma unroll
    for (int mf = 0; mf < 2; mf++)
        #pragma unroll
        for (int nf = 0; nf < 8; nf++)
            #pragma unroll
            for (int i = 0; i < 4; i++) acc[mf][nf][i] = 0.f;

    const int nt = K / BK;
    const int a_row_off = ((lane >> 3) & 1) * 8 + lm;
    const int a_col_off = (lane >> 4) * 8;
    const int b_row_off = (lane >> 4) * 8 + lm;
    const int b_col_off = ((lane >> 3) & 1) * 8;

    auto load_stage = [&](int s, int k0) {
        __half* Ast = As + s * STAGE_HALVES;
        __half* Bst = Bs + s * STAGE_HALVES;
        #pragma unroll
        for (int i = 0; i < 2; i++) {
            int row = lr + i * 64;
            cp16(smem_u32(&Ast[row * SLD + lc]),
                 A + (int64_t)(bm + row) * lda + zoff + k0 + lc, true);
        }
        #pragma unroll
        for (int i = 0; i < 2; i++) {
            int row = lr + i * 64;
            cp16(smem_u32(&Bst[row * SLD + lc]),
                 B + (int64_t)(bn + row) * ldb + zoff + k0 + lc, (bn + row) < N);
        }
        asm volatile("cp.async.commit_group;\n");
    };

    #pragma unroll
    for (int s = 0; s < STG - 1; s++) load_stage(s, s * BK);

    for (int t = 0; t < nt; t++) {
        const int s = t % STG;
        asm volatile("cp.async.wait_group %0;\n" :: "n"(STG - 2));
        __syncthreads();   // single barrier: orders prev-stage reads before refill

        int tn = t + STG - 1;
        if (tn < nt) load_stage(tn % STG, tn * BK);

        const __half* Ast = As + s * STAGE_HALVES;
        const __half* Bst = Bs + s * STAGE_HALVES;
        #pragma unroll
        for (int kk = 0; kk < BK; kk += 16) {
            uint32_t a[2][4], b[8][2];
            #pragma unroll
            for (int mf = 0; mf < 2; mf++) {
                uint32_t addr = smem_u32(&Ast[(wm + mf * 16 + a_row_off) * SLD + kk + a_col_off]);
                ldsm_x4(a[mf][0], a[mf][1], a[mf][2], a[mf][3], addr);
            }
            #pragma unroll
            for (int p = 0; p < 4; p++) {
                uint32_t addr = smem_u32(&Bst[(wn + p * 16 + b_row_off) * SLD + kk + b_col_off]);
                ldsm_x4(b[2 * p][0], b[2 * p][1], b[2 * p + 1][0], b[2 * p + 1][1], addr);
            }
            #pragma unroll
            for (int mf = 0; mf < 2; mf++)
                #pragma unroll
                for (int nf = 0; nf < 8; nf++)
                    asm volatile(
                        "mma.sync.aligned.m16n8k16.row.col.f32.f16.f16.f32 "
                        "{%0,%1,%2,%3}, {%4,%5,%6,%7}, {%8,%9}, {%0,%1,%2,%3};\n"
                        : "+f"(acc[mf][nf][0]), "+f"(acc[mf][nf][1]),
                          "+f"(acc[mf][nf][2]), "+f"(acc[mf][nf][3])
                        : "r"(a[mf][0]), "r"(a[mf][1]), "r"(a[mf][2]), "r"(a[mf][3]),
                          "r"(b[nf][0]), "r"(b[nf][1]));
        }
    }

    #pragma unroll
    for (int mf = 0; mf < 2; mf++) {
        int r0 = bm + wm + mf * 16 + g;
        #pragma unroll
        for (int nf = 0; nf < 8; nf++) {
            int c = bn + wn + nf * 8 + 2 * tg;
            if (c + 1 < N) {
                __stcs((float2*)&Cz[(int64_t)r0 * ldc + c],
                       make_float2(acc[mf][nf][0], acc[mf][nf][1]));
                __stcs((float2*)&Cz[(int64_t)(r0 + 8) * ldc + c],
                       make_float2(acc[mf][nf][2], acc[mf][nf][3]));
            } else if (c < N) {
                Cz[(int64_t)r0 * ldc + c]       = acc[mf][nf][0];
                Cz[(int64_t)(r0 + 8) * ldc + c] = acc[mf][nf][2];
            }
        }
    }
}

// ===== MAIN GEMM: R9-EXACT (128x128, 8 warps, BK=32, 5 stages, 2 CTA/SM,
//       compile-time strides, single barrier per k-tile, streaming stores) =====
#define GNT (KCAT / BK)     // 132

__global__ __launch_bounds__(256, 2)
void gemm_big(const __half* __restrict__ A, const __half* __restrict__ B,
              float* __restrict__ C) {
    extern __shared__ __half sm[];
    __half* As = sm;
    __half* Bs = sm + STG * STAGE_HALVES;

    const int tid  = threadIdx.x;
    const int warp = tid >> 5;
    const int lane = tid & 31;
    const int g    = lane >> 2;
    const int tg   = lane & 3;
    const int lm   = lane & 7;
    const int wm   = (warp & 3) * 32;   // 4 warps along M
    const int wn   = (warp >> 2) * 64;  // 2 warps along N
    const int bm   = blockIdx.y * BM;
    const int bn   = blockIdx.x * BN;

    const int lr = tid >> 2;
    const int lc = (tid & 3) * 8;

    float acc[2][8][4];
    #pragma unroll
    for (int mf = 0; mf < 2; mf++)
        #pragma unroll
        for (int nf = 0; nf < 8; nf++)
            #pragma unroll
            for (int i = 0; i < 4; i++) acc[mf][nf][i] = 0.f;

    const int a_row_off = ((lane >> 3) & 1) * 8 + lm;
    const int a_col_off = (lane >> 4) * 8;
    const int b_row_off = (lane >> 4) * 8 + lm;
    const int b_col_off = ((lane >> 3) & 1) * 8;

    auto load_stage = [&](int s, int k0) {
        __half* Ast = As + s * STAGE_HALVES;
        __half* Bst = Bs + s * STAGE_HALVES;
        #pragma unroll
        for (int i = 0; i < 2; i++) {
            int row = lr + i * 64;
            cp16(smem_u32(&Ast[row * SLD + lc]),
                 A + (int64_t)(bm + row) * KCAT + k0 + lc, true);
        }
        #pragma unroll
        for (int i = 0; i < 2; i++) {
            int row = lr + i * 64;
            cp16(smem_u32(&Bst[row * SLD + lc]),
                 B + (int64_t)(bn + row) * KCAT + k0 + lc, true);
        }
        asm volatile("cp.async.commit_group;\n");
    };

    #pragma unroll
    for (int s = 0; s < STG - 1; s++) load_stage(s, s * BK);

    for (int t = 0; t < GNT; t++) {
        const int s = t % STG;
        asm volatile("cp.async.wait_group %0;\n" :: "n"(STG - 2));
        __syncthreads();   // single barrier: all warps done reading stage (t-1)%STG

        int tn = t + STG - 1;
        if (tn < GNT) load_stage(tn % STG, tn * BK);

        const __half* Ast = As + s * STAGE_HALVES;
        const __half* Bst = Bs + s * STAGE_HALVES;
        #pragma unroll
        for (int kk = 0; kk < BK; kk += 16) {
            uint32_t a[2][4], b[8][2];
            #pragma unroll
            for (int mf = 0; mf < 2; mf++) {
                uint32_t addr = smem_u32(&Ast[(wm + mf * 16 + a_row_off) * SLD + kk + a_col_off]);
                ldsm_x4(a[mf][0], a[mf][1], a[mf][2], a[mf][3], addr);
            }
            #pragma unroll
            for (int p = 0; p < 4; p++) {
                uint32_t addr = smem_u32(&Bst[(wn + p * 16 + b_row_off) * SLD + kk + b_col_off]);
                ldsm_x4(b[2 * p][0], b[2 * p][1], b[2 * p + 1][0], b[2 * p + 1][1], addr);
            }
            #pragma unroll
            for (int mf = 0; mf < 2; mf++)
                #pragma unroll
                for (int nf = 0; nf < 8; nf++)
                    asm volatile(
                        "mma.sync.aligned.m16n8k16.row.col.f32.f16.f16.f32 "
                        "{%0,%1,%2,%3}, {%4,%5,%6,%7}, {%8,%9}, {%0,%1,%2,%3};\n"
                        : "+f"(acc[mf][nf][0]), "+f"(acc[mf][nf][1]),
                          "+f"(acc[mf][nf][2]), "+f"(acc[mf][nf][3])
                        : "r"(a[mf][0]), "r"(a[mf][1]), "r"(a[mf][2]), "r"(a[mf][3]),
                          "r"(b[nf][0]), "r"(b[nf][1]));
        }
    }

    // epilogue: streaming stores (C is write-once; keep B resident in L2)
    #pragma unroll
    for (int mf = 0; mf < 2; mf++) {
        int r0 = bm + wm + mf * 16 + g;
        #pragma unroll
        for (int nf = 0; nf < 8; nf++) {
            int c = bn + wn + nf * 8 + 2 * tg;
            __stcs((float2*)&C[(int64_t)r0 * OUT_F + c],
                   make_float2(acc[mf][nf][0], acc[mf][nf][1]));
            __stcs((float2*)&C[(int64_t)(r0 + 8) * OUT_F + c],
                   make_float2(acc[mf][nf][2], acc[mf][nf][3]));
        }
    }
}

// ===================== launch =====================
extern "C" void kernel_launch(void* const* d_in, const int* in_sizes, int n_in,
                              void* d_out, int out_size) {
    const float* x  = (const float*)d_in[0];  // [8192, 4096]
    const float* W0 = (const float*)d_in[1];  // [4096, 4096]
    const float* Wg = (const float*)d_in[2];  // [8, 4096]
    const float* A  = (const float*)d_in[3];  // [8, 16, 4096]
    const float* B  = (const float*)d_in[4];  // [8, 4096, 16]
    float* out = (float*)d_out;               // [8192, 4096]

    __half *Xcat, *Wcat, *WgA;
    float* P;
    cudaGetSymbolAddress((void**)&Xcat, g_Xcat);
    cudaGetSymbolAddress((void**)&Wcat, g_Wcat);
    cudaGetSymbolAddress((void**)&WgA,  g_WgA);
    cudaGetSymbolAddress((void**)&P,    g_P);

    cudaFuncSetAttribute(gemm_f16_ms, cudaFuncAttributeMaxDynamicSharedMemorySize, DYN_SMEM);
    cudaFuncSetAttribute(gemm_big,    cudaFuncAttributeMaxDynamicSharedMemorySize, DYN_SMEM);

    // launch 1: x -> Xcat fp16  +  [Wg;A] -> WgA fp16
    conv_x_kernel<<<4096, 256>>>((const float4*)x, Wg, A, Xcat, WgA);

    // launch 2: W0/Bmat -> Wcat fp16
    conv_w_kernel<<<4096, 256>>>((const float4*)W0, B, Wcat);

    // launch 3: skinny gate GEMM (split-K=4)
    gemm_f16_ms<<<dim3(2, NROWS / BM, KSPLIT), 256, DYN_SMEM>>>(
        Xcat, WgA, P, NROWS, P_COLS, IN_F / KSPLIT, KCAT, IN_F, P_COLS);

    // launch 4: softmax gate + split-K reduce + pack H
    softmax_pack_kernel<<<NROWS, 128>>>(P, Xcat);

    // launch 5: main GEMM (R9-exact)
    gemm_big<<<dim3(OUT_F / BN, NROWS / BM), 256, DYN_SMEM>>>(Xcat, Wcat, out);
}